// round 2
// baseline (speedup 1.0000x reference)
#include <cuda_runtime.h>
#include <math.h>

// GaussianScorer: out[m, l] = logc - 0.5*e2[m] - 0.5*m2[l] + cross[m, l]
//   m in [0, B*S), l in [0, L)
//   cross = sum_k emb'[m,k] * means'[l,k],  emb' = emb * rsqrt(var), means' = means * rsqrt(var)
//   e2    = sum_k emb'^2,  m2 = sum_k means'^2
//   logc  = -E/2 * ln(2*pi) - 0.5 * sum_k log(var[k])
//
// Shapes: B=8, S=2048, E=512, L=128  ->  GEMM M=16384, N=128, K=512.

#define GS_M 16384
#define GS_K 512
#define GS_L 128

#define BM 128
#define BN 128
#define BK 32
#define TM 8
#define TN 8
#define NTHREADS 256     // (BM/TM) * (BN/TN)
#define LDT 132          // padded lead dim for transposed smem tiles

__global__ __launch_bounds__(NTHREADS, 1)
void gs_kernel(const float* __restrict__ emb,
               const float* __restrict__ means,
               const float* __restrict__ var,
               float* __restrict__ out) {
    __shared__ float As[BK][LDT];   // emb tile, transposed [k][m], scaled by rsqrt(var)
    __shared__ float Bs[BK][LDT];   // means tile, transposed [k][l], scaled by rsqrt(var)
    __shared__ float sInvStd[GS_K]; // rsqrt(var[k])
    __shared__ float sRed[8];
    __shared__ float sLogc;

    const int tid = threadIdx.x;

    // ---- prologue: rsqrt(var) into smem + logc block-reduction ----
    float lv = 0.0f;
    #pragma unroll
    for (int i = tid; i < GS_K; i += NTHREADS) {
        float v = var[i];
        sInvStd[i] = rsqrtf(v);
        lv += logf(v);
    }
    #pragma unroll
    for (int o = 16; o > 0; o >>= 1)
        lv += __shfl_xor_sync(0xffffffffu, lv, o);
    if ((tid & 31) == 0) sRed[tid >> 5] = lv;
    __syncthreads();
    if (tid == 0) {
        float s = 0.0f;
        #pragma unroll
        for (int w = 0; w < 8; w++) s += sRed[w];
        // factor = -E/2 * ln(2*pi)
        const float FACTOR = -256.0f * 1.8378770664093453f;
        sLogc = FACTOR - 0.5f * s;
    }
    // first loop-top __syncthreads() orders sInvStd / sLogc for everyone

    const int m0 = blockIdx.x * BM;
    const int tn = tid & 15;         // 0..15 -> column group
    const int tm = tid >> 4;         // 0..15 -> row group

    float acc[TM][TN];
    float e2[TM];
    float b2[TN];
    #pragma unroll
    for (int i = 0; i < TM; i++) {
        e2[i] = 0.0f;
        #pragma unroll
        for (int j = 0; j < TN; j++) acc[i][j] = 0.0f;
    }
    #pragma unroll
    for (int j = 0; j < TN; j++) b2[j] = 0.0f;

    const float* embBase = emb + (size_t)m0 * GS_K;

    for (int kt = 0; kt < GS_K; kt += BK) {
        __syncthreads();  // writes below vs reads of previous tile (and prologue on iter 0)

        // ---- load + scale + transpose tiles: 4 float4 chunks per thread per tile ----
        #pragma unroll
        for (int i = 0; i < 4; i++) {
            int c = tid + NTHREADS * i;      // 0..1023
            int row = c >> 3;                // 0..127
            int kc = (c & 7) << 2;           // 0,4,...,28

            float4 s4 = *(const float4*)(&sInvStd[kt + kc]);

            float4 a4 = *(const float4*)(embBase + (size_t)row * GS_K + kt + kc);
            As[kc + 0][row] = a4.x * s4.x;
            As[kc + 1][row] = a4.y * s4.y;
            As[kc + 2][row] = a4.z * s4.z;
            As[kc + 3][row] = a4.w * s4.w;

            float4 b4 = *(const float4*)(means + (size_t)row * GS_K + kt + kc);
            Bs[kc + 0][row] = b4.x * s4.x;
            Bs[kc + 1][row] = b4.y * s4.y;
            Bs[kc + 2][row] = b4.z * s4.z;
            Bs[kc + 3][row] = b4.w * s4.w;
        }
        __syncthreads();

        // ---- compute ----
        #pragma unroll
        for (int k = 0; k < BK; k++) {
            float a[TM], b[TN];
            *(float4*)&a[0] = *(const float4*)&As[k][tm * TM];
            *(float4*)&a[4] = *(const float4*)&As[k][tm * TM + 4];
            *(float4*)&b[0] = *(const float4*)&Bs[k][tn * TN];
            *(float4*)&b[4] = *(const float4*)&Bs[k][tn * TN + 4];

            #pragma unroll
            for (int i = 0; i < TM; i++) e2[i] = fmaf(a[i], a[i], e2[i]);
            #pragma unroll
            for (int j = 0; j < TN; j++) b2[j] = fmaf(b[j], b[j], b2[j]);
            #pragma unroll
            for (int i = 0; i < TM; i++)
                #pragma unroll
                for (int j = 0; j < TN; j++)
                    acc[i][j] = fmaf(a[i], b[j], acc[i][j]);
        }
    }

    const float logc = sLogc;

    // ---- epilogue: out[m, l] = logc - 0.5*e2 - 0.5*m2 + cross ----
    #pragma unroll
    for (int i = 0; i < TM; i++) {
        int m = m0 + tm * TM + i;
        float base = logc - 0.5f * e2[i];
        float4 o0, o1;
        o0.x = base - 0.5f * b2[0] + acc[i][0];
        o0.y = base - 0.5f * b2[1] + acc[i][1];
        o0.z = base - 0.5f * b2[2] + acc[i][2];
        o0.w = base - 0.5f * b2[3] + acc[i][3];
        o1.x = base - 0.5f * b2[4] + acc[i][4];
        o1.y = base - 0.5f * b2[5] + acc[i][5];
        o1.z = base - 0.5f * b2[6] + acc[i][6];
        o1.w = base - 0.5f * b2[7] + acc[i][7];
        float* op = out + (size_t)m * GS_L + tn * TN;
        *(float4*)(op)     = o0;
        *(float4*)(op + 4) = o1;
    }
}

extern "C" void kernel_launch(void* const* d_in, const int* in_sizes, int n_in,
                              void* d_out, int out_size) {
    const float* emb   = (const float*)d_in[0];   // [8, 2048, 512] f32
    const float* means = (const float*)d_in[1];   // [128, 512] f32
    const float* var   = (const float*)d_in[2];   // [512] f32
    float* out = (float*)d_out;                   // [8, 2048, 128] f32
    (void)in_sizes; (void)n_in; (void)out_size;

    gs_kernel<<<GS_M / BM, NTHREADS>>>(emb, means, var, out);
}

// round 5
// speedup vs baseline: 2.2793x; 2.2793x over previous
#include <cuda_runtime.h>
#include <math.h>
#include <stdint.h>

// GaussianScorer on GB300 (sm_103a) via mma.sync tf32 (compute_103-safe).
// out[m,l] = logc - 0.5*e2[m] - 0.5*m2[l] + cross[m,l]
//   cross[m,l] = sum_k emb[m,k] * (means[l,k]*inv_var[k])   <- tf32 mma.sync GEMM
//   e2[m]      = sum_k emb[m,k]^2 * inv_var[k]              <- fp32 SIMT from SMEM tiles
//   m2[l], logc                                             <- prep kernel
// Shapes: M=16384 (B*S), L=128, K=512.

#define GS_M 16384
#define GS_K 512
#define GS_L 128
#define BM   128
#define BKT  32
#define NITER (GS_K / BKT)   // 16
#define NSTG 4
#define NTHREADS 256

#define STAGE_BYTES 16384            // 128 rows * 128B
#define A_OFF 0
#define B_OFF (NSTG * STAGE_BYTES)   // 65536
#define IV_OFF (2 * NSTG * STAGE_BYTES)  // 131072 : 512 f32 inv_var
#define MOFF_OFF (IV_OFF + 2048)         // 128 f32 : logc - 0.5*m2[l]
#define E2_OFF (MOFF_OFF + 512)          // 256 f32 : e2 partials
#define SMEM_TOTAL (E2_OFF + 1024)       // 134656

__device__ float g_Bs[GS_L * GS_K];
__device__ float g_m2[GS_L];
__device__ float g_logc;

static __device__ __forceinline__ uint32_t smem_u32(const void* p) {
    uint32_t a;
    asm("{ .reg .u64 t; cvta.to.shared.u64 t, %1; cvt.u32.u64 %0, t; }" : "=r"(a) : "l"(p));
    return a;
}

#define CP_ASYNC16(dst, src) \
    asm volatile("cp.async.cg.shared.global [%0], [%1], 16;" :: "r"(dst), "l"(src) : "memory")
#define CP_COMMIT() asm volatile("cp.async.commit_group;" ::: "memory")
#define CP_WAIT2()  asm volatile("cp.async.wait_group 2;" ::: "memory")

// swizzled byte offset of float (row, k) inside a 128x32 f32 tile with 128B rows
#define SW_ADDR(row, k) \
    ((uint32_t)((row) * 128 + ((((k) >> 2) ^ ((row) & 7)) << 4) + ((k) & 3) * 4))

#define MMA_TF32(d, a, b)                                                     \
    asm volatile("mma.sync.aligned.m16n8k8.row.col.f32.tf32.tf32.f32 "        \
        "{%0,%1,%2,%3}, {%4,%5,%6,%7}, {%8,%9}, {%0,%1,%2,%3};"               \
        : "+f"((d)[0]), "+f"((d)[1]), "+f"((d)[2]), "+f"((d)[3])              \
        : "r"((a)[0]), "r"((a)[1]), "r"((a)[2]), "r"((a)[3]),                 \
          "r"((b)[0]), "r"((b)[1]))

// ---------------- prep: g_Bs = means * inv_var, g_m2, g_logc ----------------
__global__ void gs_prep(const float* __restrict__ means, const float* __restrict__ var) {
    __shared__ float red[4];
    const int l = blockIdx.x;
    const int t = threadIdx.x;        // 128 threads, 4 elems each
    const int i0 = t * 4;

    float4 v4 = *(const float4*)(var + i0);
    float4 m4 = *(const float4*)(means + (size_t)l * GS_K + i0);
    float4 inv = make_float4(1.0f / v4.x, 1.0f / v4.y, 1.0f / v4.z, 1.0f / v4.w);
    float4 b4 = make_float4(m4.x * inv.x, m4.y * inv.y, m4.z * inv.z, m4.w * inv.w);
    *(float4*)(g_Bs + (size_t)l * GS_K + i0) = b4;

    float m2 = m4.x * b4.x + m4.y * b4.y + m4.z * b4.z + m4.w * b4.w;
    #pragma unroll
    for (int o = 16; o > 0; o >>= 1) m2 += __shfl_xor_sync(0xffffffffu, m2, o);
    if ((t & 31) == 0) red[t >> 5] = m2;
    __syncthreads();
    if (t == 0) g_m2[l] = red[0] + red[1] + red[2] + red[3];

    if (l == 0) {
        __syncthreads();
        float lg = logf(v4.x) + logf(v4.y) + logf(v4.z) + logf(v4.w);
        #pragma unroll
        for (int o = 16; o > 0; o >>= 1) lg += __shfl_xor_sync(0xffffffffu, lg, o);
        if ((t & 31) == 0) red[t >> 5] = lg;
        __syncthreads();
        if (t == 0) {
            const float FACTOR = -256.0f * 1.8378770664093453f;   // -E/2 * ln(2*pi)
            g_logc = FACTOR - 0.5f * (red[0] + red[1] + red[2] + red[3]);
        }
    }
}

// ---------------- main kernel ----------------
__global__ __launch_bounds__(NTHREADS, 1)
void gs_main(const float* __restrict__ emb, const float* __restrict__ var,
             float* __restrict__ out) {
    extern __shared__ __align__(1024) char smem[];
    const uint32_t sb = smem_u32(smem);
    const int tid = threadIdx.x;
    const int m0 = blockIdx.x * BM;

    const int lane = tid & 31;
    const int g = lane >> 2;          // 0..7
    const int tig = lane & 3;         // 0..3
    const int wid = tid >> 5;
    const int wm = wid >> 1;          // 0..3  -> 32 rows each
    const int wn = wid & 1;           // 0..1  -> 64 cols each

    // per-block constants into smem
    if (tid < 128) {
        float4 v4 = *(const float4*)(var + tid * 4);
        *(float4*)(smem + IV_OFF + tid * 16) =
            make_float4(1.0f / v4.x, 1.0f / v4.y, 1.0f / v4.z, 1.0f / v4.w);
        ((float*)(smem + MOFF_OFF))[tid] = g_logc - 0.5f * g_m2[tid];
    }

    // stage loader: 8 x cp.async(16B) per thread (A + B), one commit group
    #define LOAD_STAGE(s, kt) do {                                              \
        _Pragma("unroll")                                                       \
        for (int _i = 0; _i < 4; _i++) {                                        \
            int _c = tid + NTHREADS * _i;                                       \
            int _r = _c >> 3, _c4 = _c & 7;                                     \
            uint32_t _so = (uint32_t)(_r * 128 + ((_c4 ^ (_r & 7)) << 4));      \
            CP_ASYNC16(sb + A_OFF + (s) * STAGE_BYTES + _so,                    \
                       emb + (size_t)(m0 + _r) * GS_K + (kt) + _c4 * 4);        \
            CP_ASYNC16(sb + B_OFF + (s) * STAGE_BYTES + _so,                    \
                       g_Bs + (size_t)_r * GS_K + (kt) + _c4 * 4);              \
        }                                                                       \
        CP_COMMIT();                                                            \
    } while (0)

    // prefetch 3 stages
    LOAD_STAGE(0, 0);
    LOAD_STAGE(1, BKT);
    LOAD_STAGE(2, 2 * BKT);

    float acc[2][8][4];
    #pragma unroll
    for (int mt = 0; mt < 2; mt++)
        #pragma unroll
        for (int nt = 0; nt < 8; nt++)
            #pragma unroll
            for (int j = 0; j < 4; j++) acc[mt][nt][j] = 0.0f;

    float e2p = 0.0f;
    const int row_e = tid & 127;      // e2 row this thread owns
    const int half = tid >> 7;        // which 16-k half of the stage
    const float* ivp = (const float*)(smem + IV_OFF);

    for (int it = 0; it < NITER; ++it) {
        CP_WAIT2();
        __syncthreads();

        const int stage = it & (NSTG - 1);
        const char* As = smem + A_OFF + stage * STAGE_BYTES;
        const char* Bs = smem + B_OFF + stage * STAGE_BYTES;

        // ---- tensor-core compute: 4 k-steps of 8 ----
        #pragma unroll
        for (int ks = 0; ks < 4; ks++) {
            const int k0 = ks * 8;
            uint32_t af[2][4], bf[8][2];
            #pragma unroll
            for (int mt = 0; mt < 2; mt++) {
                const int r0 = wm * 32 + mt * 16 + g;
                af[mt][0] = *(const uint32_t*)(As + SW_ADDR(r0,     k0 + tig));
                af[mt][1] = *(const uint32_t*)(As + SW_ADDR(r0 + 8, k0 + tig));
                af[mt][2] = *(const uint32_t*)(As + SW_ADDR(r0,     k0 + tig + 4));
                af[mt][3] = *(const uint32_t*)(As + SW_ADDR(r0 + 8, k0 + tig + 4));
            }
            #pragma unroll
            for (int nt = 0; nt < 8; nt++) {
                const int rn = wn * 64 + nt * 8 + g;
                bf[nt][0] = *(const uint32_t*)(Bs + SW_ADDR(rn, k0 + tig));
                bf[nt][1] = *(const uint32_t*)(Bs + SW_ADDR(rn, k0 + tig + 4));
            }
            #pragma unroll
            for (int mt = 0; mt < 2; mt++)
                #pragma unroll
                for (int nt = 0; nt < 8; nt++)
                    MMA_TF32(acc[mt][nt], af[mt], bf[nt]);
        }

        // ---- fused e2: this thread's 16 k-values of its row ----
        {
            const int kt = it * BKT;
            #pragma unroll
            for (int j = 0; j < 4; j++) {
                const int c = half * 4 + j;
                float4 a = *(const float4*)(As + row_e * 128 + ((c ^ (row_e & 7)) << 4));
                float4 v = *(const float4*)(ivp + kt + c * 4);
                e2p = fmaf(a.x * a.x, v.x, e2p);
                e2p = fmaf(a.y * a.y, v.y, e2p);
                e2p = fmaf(a.z * a.z, v.z, e2p);
                e2p = fmaf(a.w * a.w, v.w, e2p);
            }
        }

        __syncthreads();   // all reads of stage buffers done before refill

        if (it + 3 < NITER) {
            LOAD_STAGE((it + 3) & (NSTG - 1), (it + 3) * BKT);
        } else {
            CP_COMMIT();   // empty group keeps wait_group<2> arithmetic valid
        }
    }

    // ---- combine e2 halves ----
    ((float*)(smem + E2_OFF))[half * 128 + row_e] = e2p;
    __syncthreads();
    const float* sE2 = (const float*)(smem + E2_OFF);
    const float* moff = (const float*)(smem + MOFF_OFF);

    // ---- epilogue: out = cross + (-0.5*e2[m]) + (logc - 0.5*m2[l]) ----
    #pragma unroll
    for (int mt = 0; mt < 2; mt++) {
        const int r0 = wm * 32 + mt * 16 + g;
        const float rb0 = -0.5f * (sE2[r0] + sE2[128 + r0]);
        const float rb1 = -0.5f * (sE2[r0 + 8] + sE2[128 + r0 + 8]);
        float* orow0 = out + (size_t)(m0 + r0) * GS_L;
        float* orow1 = out + (size_t)(m0 + r0 + 8) * GS_L;
        #pragma unroll
        for (int nt = 0; nt < 8; nt++) {
            const int col = wn * 64 + nt * 8 + tig * 2;
            float2 mo = *(const float2*)(moff + col);
            float2 o0, o1;
            o0.x = acc[mt][nt][0] + rb0 + mo.x;
            o0.y = acc[mt][nt][1] + rb0 + mo.y;
            o1.x = acc[mt][nt][2] + rb1 + mo.x;
            o1.y = acc[mt][nt][3] + rb1 + mo.y;
            *(float2*)(orow0 + col) = o0;
            *(float2*)(orow1 + col) = o1;
        }
    }
}

extern "C" void kernel_launch(void* const* d_in, const int* in_sizes, int n_in,
                              void* d_out, int out_size) {
    const float* emb   = (const float*)d_in[0];   // [8, 2048, 512] f32
    const float* means = (const float*)d_in[1];   // [128, 512] f32
    const float* var   = (const float*)d_in[2];   // [512] f32
    float* out = (float*)d_out;                   // [8, 2048, 128] f32
    (void)in_sizes; (void)n_in; (void)out_size;

    cudaFuncSetAttribute(gs_main, cudaFuncAttributeMaxDynamicSharedMemorySize, SMEM_TOTAL);
    gs_prep<<<GS_L, 128>>>(means, var);
    gs_main<<<GS_M / BM, NTHREADS, SMEM_TOTAL>>>(emb, var, out);
}

// round 6
// speedup vs baseline: 3.9917x; 1.7513x over previous
#include <cuda_runtime.h>
#include <cuda_bf16.h>
#include <math.h>
#include <stdint.h>

// GaussianScorer sm_103a: bf16 mma.sync m16n8k16 + ldmatrix + cp.async pipeline.
// out[m,l] = logc - 0.5*e2[m] - 0.5*m2[l] + cross[m,l]
//   cross = bf16 GEMM: emb (cvt on the fly) x (means*inv_var) (prep, bf16)
//   e2    = fp32, fused off the LDG registers before conversion
// Shapes: M=16384, L=128, K=512.

#define GS_M 16384
#define GS_K 512
#define GS_L 128
#define BM   128
#define BKT  32
#define NITER (GS_K / BKT)   // 16
#define NSTG 4
#define NTHREADS 512

#define A_STAGE 8192                 // 128 rows * 64B (bf16)
#define B_STAGE 8192
#define A_OFF 0
#define B_OFF (NSTG * A_STAGE)       // 32768
#define IV_OFF 65536                 // 512 f32 inv_var
#define MOFF_OFF 67584               // 128 f32: logc - 0.5*m2[l]
#define E2_OFF 68096                 // 4*128 f32 partials
#define SMEM_TOTAL 70144

__device__ __nv_bfloat16 g_Bh[GS_L * GS_K];
__device__ float g_m2[GS_L];
__device__ float g_logc;

static __device__ __forceinline__ uint32_t smem_u32(const void* p) {
    uint32_t a;
    asm("{ .reg .u64 t; cvta.to.shared.u64 t, %1; cvt.u32.u64 %0, t; }" : "=r"(a) : "l"(p));
    return a;
}

#define CP_ASYNC16(dst, src) \
    asm volatile("cp.async.cg.shared.global [%0], [%1], 16;" :: "r"(dst), "l"(src) : "memory")
#define CP_COMMIT() asm volatile("cp.async.commit_group;" ::: "memory")
#define CP_WAIT2()  asm volatile("cp.async.wait_group 2;" ::: "memory")

#define LDSM_X4(r, addr)                                                        \
    asm volatile("ldmatrix.sync.aligned.m8n8.x4.shared.b16 {%0,%1,%2,%3}, [%4];" \
        : "=r"((r)[0]), "=r"((r)[1]), "=r"((r)[2]), "=r"((r)[3]) : "r"(addr))

#define MMA_BF16(d, a, b0, b1)                                                  \
    asm volatile("mma.sync.aligned.m16n8k16.row.col.f32.bf16.bf16.f32 "         \
        "{%0,%1,%2,%3}, {%4,%5,%6,%7}, {%8,%9}, {%0,%1,%2,%3};"                 \
        : "+f"((d)[0]), "+f"((d)[1]), "+f"((d)[2]), "+f"((d)[3])                \
        : "r"((a)[0]), "r"((a)[1]), "r"((a)[2]), "r"((a)[3]), "r"(b0), "r"(b1))

// swizzle: 64B rows of 4x16B chunks; chunk ^= (row>>1)&3
#define SWZ(row, chunk) ((uint32_t)((row) * 64 + (((chunk) ^ (((row) >> 1) & 3)) << 4)))

// ---------------- prep: g_Bh = bf16(means*inv_var), g_m2, g_logc ----------------
__global__ void gs_prep(const float* __restrict__ means, const float* __restrict__ var) {
    __shared__ float red[4];
    const int l = blockIdx.x;
    const int t = threadIdx.x;        // 128 threads, 4 elems each
    const int i0 = t * 4;

    float4 v4 = *(const float4*)(var + i0);
    float4 m4 = *(const float4*)(means + (size_t)l * GS_K + i0);
    float4 b4 = make_float4(m4.x / v4.x, m4.y / v4.y, m4.z / v4.z, m4.w / v4.w);

    __nv_bfloat162 p0 = __floats2bfloat162_rn(b4.x, b4.y);
    __nv_bfloat162 p1 = __floats2bfloat162_rn(b4.z, b4.w);
    *(uint2*)(g_Bh + (size_t)l * GS_K + i0) =
        make_uint2(*(uint32_t*)&p0, *(uint32_t*)&p1);

    float m2 = m4.x * b4.x + m4.y * b4.y + m4.z * b4.z + m4.w * b4.w;
    #pragma unroll
    for (int o = 16; o > 0; o >>= 1) m2 += __shfl_xor_sync(0xffffffffu, m2, o);
    if ((t & 31) == 0) red[t >> 5] = m2;
    __syncthreads();
    if (t == 0) g_m2[l] = red[0] + red[1] + red[2] + red[3];

    if (l == 0) {
        __syncthreads();
        float lg = logf(v4.x) + logf(v4.y) + logf(v4.z) + logf(v4.w);
        #pragma unroll
        for (int o = 16; o > 0; o >>= 1) lg += __shfl_xor_sync(0xffffffffu, lg, o);
        if ((t & 31) == 0) red[t >> 5] = lg;
        __syncthreads();
        if (t == 0) {
            const float FACTOR = -256.0f * 1.8378770664093453f;   // -E/2 * ln(2*pi)
            g_logc = FACTOR - 0.5f * (red[0] + red[1] + red[2] + red[3]);
        }
    }
}

// ---------------- main kernel ----------------
__global__ __launch_bounds__(NTHREADS, 1)
void gs_main(const float* __restrict__ emb, const float* __restrict__ var,
             float* __restrict__ out) {
    extern __shared__ __align__(1024) char smem[];
    const uint32_t sb = smem_u32(smem);
    const int tid = threadIdx.x;
    const int m0 = blockIdx.x * BM;

    const int lane = tid & 31;
    const int g = lane >> 2;          // 0..7
    const int tig = lane & 3;         // 0..3
    const int wid = tid >> 5;         // 0..15
    const int wm = wid >> 2;          // 0..3 -> 32 rows
    const int wn = wid & 3;           // 0..3 -> 32 cols

    const int mm = lane >> 3;         // ldmatrix matrix id 0..3
    const int mrow = lane & 7;

    // producer mapping: each thread owns (row, quarter) of a stage
    const int arow = tid >> 2;        // 0..127
    const int aq = tid & 3;           // 8 k values each
    const uint32_t sts_off = SWZ(arow, aq);

    // per-block constants into smem
    if (tid < 128) {
        float4 v4 = *(const float4*)(var + tid * 4);
        *(float4*)(smem + IV_OFF + tid * 16) =
            make_float4(1.0f / v4.x, 1.0f / v4.y, 1.0f / v4.z, 1.0f / v4.w);
        ((float*)(smem + MOFF_OFF))[tid] = g_logc - 0.5f * g_m2[tid];
    }

    const float* aSrc = emb + (size_t)(m0 + arow) * GS_K + aq * 8;
    const __nv_bfloat16* bSrc = g_Bh + (size_t)arow * GS_K + aq * 8;

    #define LDG_A(rr, kt) do {                                                   \
        rr[0] = *(const float4*)(aSrc + (kt));                                   \
        rr[1] = *(const float4*)(aSrc + (kt) + 4);                               \
    } while (0)

    #define CPASYNC_B(s, kt) do {                                                \
        CP_ASYNC16(sb + B_OFF + (s) * B_STAGE + sts_off,                         \
                   (const char*)(bSrc + (kt)));                                  \
        CP_COMMIT();                                                             \
    } while (0)

    // convert + store A stage, accumulate exact fp32 e2
    #define STS_A_E2(s, rr, kt) do {                                             \
        float4 iv0 = *(const float4*)(smem + IV_OFF + ((kt) + aq * 8) * 4);      \
        float4 iv1 = *(const float4*)(smem + IV_OFF + ((kt) + aq * 8 + 4) * 4);  \
        e2p = fmaf(rr[0].x * rr[0].x, iv0.x, e2p);                               \
        e2p = fmaf(rr[0].y * rr[0].y, iv0.y, e2p);                               \
        e2p = fmaf(rr[0].z * rr[0].z, iv0.z, e2p);                               \
        e2p = fmaf(rr[0].w * rr[0].w, iv0.w, e2p);                               \
        e2p = fmaf(rr[1].x * rr[1].x, iv1.x, e2p);                               \
        e2p = fmaf(rr[1].y * rr[1].y, iv1.y, e2p);                               \
        e2p = fmaf(rr[1].z * rr[1].z, iv1.z, e2p);                               \
        e2p = fmaf(rr[1].w * rr[1].w, iv1.w, e2p);                               \
        __nv_bfloat162 c0 = __floats2bfloat162_rn(rr[0].x, rr[0].y);             \
        __nv_bfloat162 c1 = __floats2bfloat162_rn(rr[0].z, rr[0].w);             \
        __nv_bfloat162 c2 = __floats2bfloat162_rn(rr[1].x, rr[1].y);             \
        __nv_bfloat162 c3 = __floats2bfloat162_rn(rr[1].z, rr[1].w);             \
        *(uint4*)(smem + A_OFF + (s) * A_STAGE + sts_off) =                      \
            make_uint4(*(uint32_t*)&c0, *(uint32_t*)&c1,                         \
                       *(uint32_t*)&c2, *(uint32_t*)&c3);                        \
    } while (0)

    float e2p = 0.0f;
    float4 rA[2][2];

    // ---- prologue ----
    LDG_A(rA[0], 0);
    CPASYNC_B(0, 0);
    LDG_A(rA[1], BKT);
    CPASYNC_B(1, BKT);
    CPASYNC_B(2, 2 * BKT);
    __syncthreads();                  // IV ready before e2 use
    STS_A_E2(0, rA[0], 0);

    float acc[2][4][4];
    #pragma unroll
    for (int mt = 0; mt < 2; mt++)
        #pragma unroll
        for (int nt = 0; nt < 4; nt++)
            #pragma unroll
            for (int j = 0; j < 4; j++) acc[mt][nt][j] = 0.0f;

    // ldmatrix row/swizzle components (loop-invariant)
    const int rowA0 = wm * 32 + (mm & 1) * 8 + mrow;           // mt=0
    const int rowA1 = rowA0 + 16;                              // mt=1
    const int rowB0 = wn * 32 + (mm >> 1) * 8 + mrow;          // ntp=0
    const int rowB1 = rowB0 + 16;                              // ntp=1
    const int cA = mm >> 1;          // chunk add for A
    const int cB = mm & 1;           // chunk add for B

    #pragma unroll
    for (int it = 0; it < NITER; ++it) {
        CP_WAIT2();
        __syncthreads();

        if (it + 2 < NITER) LDG_A(rA[it & 1], (it + 2) * BKT);
        if (it + 3 < NITER) { CPASYNC_B((it + 3) & (NSTG - 1), (it + 3) * BKT); }
        else                { CP_COMMIT(); }

        const uint32_t As = sb + A_OFF + (it & (NSTG - 1)) * A_STAGE;
        const uint32_t Bs = sb + B_OFF + (it & (NSTG - 1)) * B_STAGE;

        #pragma unroll
        for (int ks = 0; ks < 2; ks++) {
            const int c0 = ks * 2;
            uint32_t af[2][4], bq[2][4];
            LDSM_X4(af[0], As + SWZ(rowA0, c0 + cA));
            LDSM_X4(af[1], As + SWZ(rowA1, c0 + cA));
            LDSM_X4(bq[0], Bs + SWZ(rowB0, c0 + cB));
            LDSM_X4(bq[1], Bs + SWZ(rowB1, c0 + cB));
            #pragma unroll
            for (int mt = 0; mt < 2; mt++) {
                MMA_BF16(acc[mt][0], af[mt], bq[0][0], bq[0][1]);
                MMA_BF16(acc[mt][1], af[mt], bq[0][2], bq[0][3]);
                MMA_BF16(acc[mt][2], af[mt], bq[1][0], bq[1][1]);
                MMA_BF16(acc[mt][3], af[mt], bq[1][2], bq[1][3]);
            }
        }

        if (it + 1 < NITER)
            STS_A_E2((it + 1) & (NSTG - 1), rA[(it + 1) & 1], (it + 1) * BKT);
    }

    // ---- e2 combine ----
    ((float*)(smem + E2_OFF))[aq * 128 + arow] = e2p;
    __syncthreads();
    const float* sE2 = (const float*)(smem + E2_OFF);
    const float* moff = (const float*)(smem + MOFF_OFF);

    // ---- epilogue ----
    #pragma unroll
    for (int mt = 0; mt < 2; mt++) {
        const int r0 = wm * 32 + mt * 16 + g;
        const float rb0 = -0.5f * (sE2[r0] + sE2[128 + r0] + sE2[256 + r0] + sE2[384 + r0]);
        const float rb1 = -0.5f * (sE2[r0 + 8] + sE2[128 + r0 + 8] + sE2[256 + r0 + 8] + sE2[384 + r0 + 8]);
        float* orow0 = out + (size_t)(m0 + r0) * GS_L;
        float* orow1 = orow0 + 8 * GS_L;
        #pragma unroll
        for (int nt = 0; nt < 4; nt++) {
            const int col = wn * 32 + nt * 8 + tig * 2;
            float2 mo = *(const float2*)(moff + col);
            float2 o0, o1;
            o0.x = acc[mt][nt][0] + rb0 + mo.x;
            o0.y = acc[mt][nt][1] + rb0 + mo.y;
            o1.x = acc[mt][nt][2] + rb1 + mo.x;
            o1.y = acc[mt][nt][3] + rb1 + mo.y;
            *(float2*)(orow0 + col) = o0;
            *(float2*)(orow1 + col) = o1;
        }
    }
}

extern "C" void kernel_launch(void* const* d_in, const int* in_sizes, int n_in,
                              void* d_out, int out_size) {
    const float* emb   = (const float*)d_in[0];   // [8, 2048, 512] f32
    const float* means = (const float*)d_in[1];   // [128, 512] f32
    const float* var   = (const float*)d_in[2];   // [512] f32
    float* out = (float*)d_out;                   // [8, 2048, 128] f32
    (void)in_sizes; (void)n_in; (void)out_size;

    cudaFuncSetAttribute(gs_main, cudaFuncAttributeMaxDynamicSharedMemorySize, SMEM_TOTAL);
    gs_prep<<<GS_L, 128>>>(means, var);
    gs_main<<<GS_M / BM, NTHREADS, SMEM_TOTAL>>>(emb, var, out);
}